// round 3
// baseline (speedup 1.0000x reference)
#include <cuda_runtime.h>
#include <cuda_bf16.h>

// Problem dims (fixed by reference)
#define Bdim   8
#define Ndim   32
#define Cdim   768
#define Tdim   256
#define Pdim   16
#define KTOP   5
#define BNprod (Bdim * Ndim)   // 256

// Output layout (float32, concatenated in return-tuple order)
#define OFF_ID      0            // id_src        (B,K)        = 40
#define OFF_SCORE   40           // score_src     (B,K)        = 40
#define OFF_SPTS    80           // score_pts     (B,K,T)      = 10240
#define OFF_TAR     10320        // tar_pts       (B,K,T,2)    = 20480
#define OFF_SRC     30800        // src_pts       (B,K,T,2)    = 20480
#define OFF_CNT     51280        // match_counts  (B,N)        = 256
// total 51536

// Scratch (no cudaMalloc allowed)
__device__ unsigned long long g_t2s[BNprod * Tdim];   // packed (score, ~argmax_s) per (b,n,t)
__device__ unsigned long long g_s2t[BNprod * Tdim];   // packed (score, ~argmax_t) per (b,n,s)
__device__ float              g_mask_all[BNprod * Tdim];
__device__ float              g_simavg[BNprod];
__device__ int                g_sel[Bdim * KTOP];

#define INIT_PACK 0x00000000FFFFFFFFULL   // score=0.0, idx=0

static __device__ __forceinline__ unsigned long long fma2(unsigned long long a,
                                                          unsigned long long b,
                                                          unsigned long long c) {
    unsigned long long d;
    asm("fma.rn.f32x2 %0, %1, %2, %3;" : "=l"(d) : "l"(a), "l"(b), "l"(c));
    return d;
}
static __device__ __forceinline__ unsigned long long dup2(float x) {
    unsigned long long r;
    asm("mov.b64 %0, {%1, %1};" : "=l"(r) : "f"(x));
    return r;
}
static __device__ __forceinline__ float2 unpk(unsigned long long v) {
    float2 f;
    asm("mov.b64 {%0, %1}, %2;" : "=f"(f.x), "=f"(f.y) : "l"(v));
    return f;
}
static __device__ __forceinline__ unsigned long long packsi(float score, int idx) {
    return ((unsigned long long)__float_as_uint(score) << 32) |
           (unsigned long long)(unsigned)(~idx);
}
static __device__ __forceinline__ unsigned long long umaxll(unsigned long long a,
                                                            unsigned long long b) {
    return a > b ? a : b;
}

// ---------------------------------------------------------------------------
// Kernel 0: reset packed max arrays (graph replays must be deterministic)
// ---------------------------------------------------------------------------
__global__ void init_kernel() {
    int i = blockIdx.x * blockDim.x + threadIdx.x;
    if (i < BNprod * Tdim) {
        g_t2s[i] = INIT_PACK;
        g_s2t[i] = INIT_PACK;
    }
}

// ---------------------------------------------------------------------------
// Kernel 1: fused fp32 GEMM (f32x2 pipe) + norm + mask + threshold + dual max
// One CTA per 128x128 tile of the 256x256 sim matrix of one (b,n).
// grid.x = B*N*4, block = 256 threads, 8x8 outputs/thread (4x f32x2 x 8)
// ---------------------------------------------------------------------------
__global__ __launch_bounds__(256, 2)
void sim_gemm(const float* __restrict__ tar,   // (B, C, T)
              const float* __restrict__ src,   // (B, N, C, T)
              const float* __restrict__ srcm,  // (B, N, T)
              const float* __restrict__ tarm)  // (B, T)
{
    const int tid = threadIdx.x;
    const int blk = blockIdx.x;
    const int bn  = blk >> 2;
    const int sub = blk & 3;
    const int b   = bn >> 5;
    const int t0  = (sub >> 1) << 7;
    const int s0  = (sub & 1) << 7;

    const float* A  = tar + (size_t)b  * Cdim * Tdim;   // [C][T]
    const float* Bp = src + (size_t)bn * Cdim * Tdim;   // [C][S]

    __shared__ __align__(16) float As[8][128];
    __shared__ __align__(16) float Bs[8][128];
    __shared__ float fA[128], fB[128];                  // sumsq -> inv_norm*mask
    __shared__ unsigned long long rowp[128], colp[128];

    if (tid < 128) { fA[tid] = 0.f; rowp[tid] = 0ULL; }
    else           { fB[tid - 128] = 0.f; colp[tid - 128] = 0ULL; }

    const int r     = tid >> 5;          // k-row within 8-slice
    const int tcol  = (tid & 31) << 2;   // float4 column
    const int ty    = tid >> 4;
    const int tx    = tid & 15;
    const int trow0 = ty << 3;
    const int scol0 = tx << 3;

    unsigned long long acc[4][8];
#pragma unroll
    for (int i = 0; i < 4; i++)
#pragma unroll
        for (int j = 0; j < 8; j++) acc[i][j] = 0ULL;

    float sqa[4] = {0.f, 0.f, 0.f, 0.f};
    float sqb[4] = {0.f, 0.f, 0.f, 0.f};

    const float* Aload = A  + (size_t)r * Tdim + t0 + tcol;
    const float* Bload = Bp + (size_t)r * Tdim + s0 + tcol;

    __syncthreads();

    for (int kc = 0; kc < Cdim; kc += 8) {
        float4 av = *(const float4*)(Aload + (size_t)kc * Tdim);
        float4 bv = *(const float4*)(Bload + (size_t)kc * Tdim);
        *(float4*)&As[r][tcol] = av;
        *(float4*)&Bs[r][tcol] = bv;
        sqa[0] += av.x * av.x; sqa[1] += av.y * av.y;
        sqa[2] += av.z * av.z; sqa[3] += av.w * av.w;
        sqb[0] += bv.x * bv.x; sqb[1] += bv.y * bv.y;
        sqb[2] += bv.z * bv.z; sqb[3] += bv.w * bv.w;
        __syncthreads();

#pragma unroll
        for (int k = 0; k < 8; k++) {
            unsigned long long a2[4];
#pragma unroll
            for (int i = 0; i < 4; i++)
                a2[i] = *(const unsigned long long*)&As[k][trow0 + 2 * i];
            float4 b0 = *(const float4*)&Bs[k][scol0];
            float4 b1 = *(const float4*)&Bs[k][scol0 + 4];
            unsigned long long bd[8];
            bd[0] = dup2(b0.x); bd[1] = dup2(b0.y);
            bd[2] = dup2(b0.z); bd[3] = dup2(b0.w);
            bd[4] = dup2(b1.x); bd[5] = dup2(b1.y);
            bd[6] = dup2(b1.z); bd[7] = dup2(b1.w);
#pragma unroll
            for (int i = 0; i < 4; i++)
#pragma unroll
                for (int j = 0; j < 8; j++)
                    acc[i][j] = fma2(a2[i], bd[j], acc[i][j]);
        }
        __syncthreads();
    }

    // Fused norms: merge per-thread partial sum-of-squares
    atomicAdd(&fA[tcol + 0], sqa[0]); atomicAdd(&fA[tcol + 1], sqa[1]);
    atomicAdd(&fA[tcol + 2], sqa[2]); atomicAdd(&fA[tcol + 3], sqa[3]);
    atomicAdd(&fB[tcol + 0], sqb[0]); atomicAdd(&fB[tcol + 1], sqb[1]);
    atomicAdd(&fB[tcol + 2], sqb[2]); atomicAdd(&fB[tcol + 3], sqb[3]);
    __syncthreads();

    if (tid < 128) {
        float inv = 1.0f / fmaxf(sqrtf(fA[tid]), 1e-12f);
        fA[tid] = inv * tarm[b * Tdim + t0 + tid];
    } else {
        int s = tid - 128;
        float inv = 1.0f / fmaxf(sqrtf(fB[s]), 1e-12f);
        fB[s] = inv * srcm[bn * Tdim + s0 + s];
    }
    __syncthreads();

    // Epilogue: scale, threshold, packed dual max/argmax
    unsigned long long colc[8];
#pragma unroll
    for (int j = 0; j < 8; j++) colc[j] = 0ULL;

#pragma unroll
    for (int i = 0; i < 4; i++) {
        const int tg0 = t0 + trow0 + 2 * i;
        const int tg1 = tg0 + 1;
        const float fa0 = fA[trow0 + 2 * i];
        const float fa1 = fA[trow0 + 2 * i + 1];
        unsigned long long row0 = 0ULL, row1 = 0ULL;
#pragma unroll
        for (int j = 0; j < 8; j++) {
            float2 p = unpk(acc[i][j]);
            float fb = fB[scol0 + j];
            float v0 = p.x * fa0 * fb; if (v0 < 0.05f) v0 = 0.f;
            float v1 = p.y * fa1 * fb; if (v1 < 0.05f) v1 = 0.f;
            const int sg = s0 + scol0 + j;
            row0 = umaxll(row0, packsi(v0, sg));
            row1 = umaxll(row1, packsi(v1, sg));
            colc[j] = umaxll(colc[j], umaxll(packsi(v0, tg0), packsi(v1, tg1)));
        }
        atomicMax(&rowp[trow0 + 2 * i],     row0);
        atomicMax(&rowp[trow0 + 2 * i + 1], row1);
    }
#pragma unroll
    for (int j = 0; j < 8; j++) atomicMax(&colp[scol0 + j], colc[j]);
    __syncthreads();

    if (tid < 128) atomicMax(&g_t2s[bn * Tdim + t0 + tid], rowp[tid]);
    else           atomicMax(&g_s2t[bn * Tdim + s0 + (tid - 128)], colp[tid - 128]);
}

// ---------------------------------------------------------------------------
// Kernel 2: cycle consistency + masks + match_counts + sim_avg
// grid = B*N, block = T
// ---------------------------------------------------------------------------
__global__ void stage2(const float* __restrict__ srcm,
                       const float* __restrict__ tarm,
                       float* __restrict__ out)
{
    const int bn = blockIdx.x;
    const int b  = bn >> 5;
    const int t  = threadIdx.x;

    unsigned long long pt = g_t2s[bn * Tdim + t];
    float sc_t2s = __uint_as_float((unsigned)(pt >> 32));
    int   i_t2s  = (int)(~(unsigned)pt);

    unsigned long long pst = g_s2t[bn * Tdim + t];
    int i_s2t_here = (int)(~(unsigned)pst);

    unsigned long long psi = g_s2t[bn * Tdim + i_t2s];
    float sc_s2t_i = __uint_as_float((unsigned)(psi >> 32));
    int   i_s2s    = (int)(~(unsigned)psi);

    int dx = (i_s2s & 15) - (t & 15);
    int dy = (i_s2s >> 4) - (t >> 4);
    bool cyc  = (dx * dx + dy * dy <= 4) && (sc_s2t_i >= 0.05f);
    bool msim = (sc_t2s >= 0.05f);

    float m = 0.f;
    if (msim && cyc && i_s2t_here != 0 && i_t2s != 0)
        m = tarm[b * Tdim + t] * srcm[bn * Tdim + i_t2s];

    g_mask_all[bn * Tdim + t] = m;

    __shared__ float s1[Tdim], s2[Tdim];
    s1[t] = m;
    s2[t] = sc_t2s * m;
    __syncthreads();
    for (int off = Tdim / 2; off > 0; off >>= 1) {
        if (t < off) { s1[t] += s1[t + off]; s2[t] += s2[t + off]; }
        __syncthreads();
    }
    if (t == 0) {
        float cnt = s1[0];
        out[OFF_CNT + bn] = cnt;
        g_simavg[bn] = (cnt > 0.f) ? (s2[0] * (1.0f / 256.0f)) : 0.f;
    }
}

// ---------------------------------------------------------------------------
// Kernel 3: top-K template selection (stable ties = ascending index)
// grid = B
// ---------------------------------------------------------------------------
__global__ void stage3(float* __restrict__ out)
{
    const int b = blockIdx.x;
    if (threadIdx.x != 0) return;
    float sa[Ndim];
    bool used[Ndim];
#pragma unroll
    for (int n = 0; n < Ndim; n++) { sa[n] = g_simavg[b * Ndim + n]; used[n] = false; }
    for (int k = 0; k < KTOP; k++) {
        float best = -1.f; int bi = 0;
        for (int n = 0; n < Ndim; n++)
            if (!used[n] && sa[n] > best) { best = sa[n]; bi = n; }
        used[bi] = true;
        g_sel[b * KTOP + k] = bi;
        out[OFF_ID    + b * KTOP + k] = (float)bi;
        out[OFF_SCORE + b * KTOP + k] = best;
    }
}

// ---------------------------------------------------------------------------
// Kernel 4: format predictions for the selected templates
// grid = B*K, block = T
// ---------------------------------------------------------------------------
__global__ void stage4(float* __restrict__ out)
{
    const int bk = blockIdx.x;
    const int b  = bk / KTOP;
    const int n  = g_sel[bk];
    const int t  = threadIdx.x;
    const int bnT = (b * Ndim + n) * Tdim + t;

    unsigned long long pt = g_t2s[bnT];
    float sc = __uint_as_float((unsigned)(pt >> 32));
    int  idx = (int)(~(unsigned)pt);
    float m  = g_mask_all[bnT];

    out[OFF_SPTS + bk * Tdim + t] = sc;
    const int o = (bk * Tdim + t) * 2;
    if (m != 0.f) {
        out[OFF_TAR + o]     = (float)(t & 15);
        out[OFF_TAR + o + 1] = (float)(t >> 4);
        out[OFF_SRC + o]     = (float)(idx & 15);
        out[OFF_SRC + o + 1] = (float)(idx >> 4);
    } else {
        out[OFF_TAR + o]     = -1.f;
        out[OFF_TAR + o + 1] = -1.f;
        out[OFF_SRC + o]     = -1.f;
        out[OFF_SRC + o + 1] = -1.f;
    }
}

// ---------------------------------------------------------------------------
extern "C" void kernel_launch(void* const* d_in, const int* in_sizes, int n_in,
                              void* d_out, int out_size)
{
    const float* src  = (const float*)d_in[0];   // src_feats (B,N,C,P,P)
    const float* tar  = (const float*)d_in[1];   // tar_feat  (B,C,P,P)
    const float* srcm = (const float*)d_in[2];   // src_masks (B,N,P,P)
    const float* tarm = (const float*)d_in[3];   // tar_mask  (B,P,P)
    float* out = (float*)d_out;

    init_kernel<<<BNprod * Tdim / 256, 256>>>();
    sim_gemm<<<BNprod * 4, 256>>>(tar, src, srcm, tarm);
    stage2<<<BNprod, Tdim>>>(srcm, tarm, out);
    stage3<<<Bdim, 32>>>(out);
    stage4<<<Bdim * KTOP, Tdim>>>(out);
}

// round 5
// speedup vs baseline: 1.7027x; 1.7027x over previous
#include <cuda_runtime.h>
#include <cuda_fp16.h>
#include <cstdint>

#define Bdim   8
#define Ndim   32
#define Cdim   768
#define Tdim   256
#define KTOP   5
#define BNprod (Bdim * Ndim)

// Output layout (float32, concatenated in return-tuple order)
#define OFF_ID      0
#define OFF_SCORE   40
#define OFF_SPTS    80
#define OFF_TAR     10320
#define OFF_SRC     30800
#define OFF_CNT     51280

__device__ unsigned long long g_t2s[BNprod * Tdim];
__device__ unsigned long long g_s2t[BNprod * Tdim];
__device__ float              g_mask_all[BNprod * Tdim];
__device__ float              g_simavg[BNprod];

#define INIT_PACK 0x00000000FFFFFFFFULL

static __device__ __forceinline__ unsigned long long packsi(float score, int idx) {
    return ((unsigned long long)__float_as_uint(score) << 32) |
           (unsigned long long)(unsigned)(~idx);
}
static __device__ __forceinline__ unsigned long long umaxll(unsigned long long a,
                                                            unsigned long long b) {
    return a > b ? a : b;
}
static __device__ __forceinline__ uint32_t smem_u32(const void* p) {
    uint32_t a;
    asm("{ .reg .u64 t; cvta.to.shared.u64 t, %1; cvt.u32.u64 %0, t; }" : "=r"(a) : "l"(p));
    return a;
}
static __device__ __forceinline__ void ldm4t(uint32_t* r, uint32_t addr) {
    asm volatile("ldmatrix.sync.aligned.m8n8.x4.trans.shared.b16 {%0,%1,%2,%3}, [%4];"
                 : "=r"(r[0]), "=r"(r[1]), "=r"(r[2]), "=r"(r[3]) : "r"(addr));
}
static __device__ __forceinline__ void mma16816(float* d, const uint32_t* a,
                                                const uint32_t* b) {
    asm volatile(
        "mma.sync.aligned.m16n8k16.row.col.f32.f16.f16.f32 "
        "{%0,%1,%2,%3}, {%4,%5,%6,%7}, {%8,%9}, {%0,%1,%2,%3};"
        : "+f"(d[0]), "+f"(d[1]), "+f"(d[2]), "+f"(d[3])
        : "r"(a[0]), "r"(a[1]), "r"(a[2]), "r"(a[3]), "r"(b[0]), "r"(b[1]));
}
static __device__ __forceinline__ void sts64(uint32_t addr, uint32_t r0, uint32_t r1) {
    asm volatile("st.shared.v2.b32 [%0], {%1, %2};" :: "r"(addr), "r"(r0), "r"(r1)
                 : "memory");
}

// convert float4 -> fp16 hi/lo pairs, accumulate sum of squares
static __device__ __forceinline__ void cvt4(float4 v, float* sq,
                                            uint32_t& hi0, uint32_t& hi1,
                                            uint32_t& lo0, uint32_t& lo1) {
    sq[0] = fmaf(v.x, v.x, sq[0]);
    sq[1] = fmaf(v.y, v.y, sq[1]);
    sq[2] = fmaf(v.z, v.z, sq[2]);
    sq[3] = fmaf(v.w, v.w, sq[3]);
    __half hx = __float2half_rn(v.x), hy = __float2half_rn(v.y);
    __half hz = __float2half_rn(v.z), hw = __float2half_rn(v.w);
    __half lx = __float2half_rn(v.x - __half2float(hx));
    __half ly = __float2half_rn(v.y - __half2float(hy));
    __half lz = __float2half_rn(v.z - __half2float(hz));
    __half lw = __float2half_rn(v.w - __half2float(hw));
    hi0 = __half_as_ushort(hx) | ((uint32_t)__half_as_ushort(hy) << 16);
    hi1 = __half_as_ushort(hz) | ((uint32_t)__half_as_ushort(hw) << 16);
    lo0 = __half_as_ushort(lx) | ((uint32_t)__half_as_ushort(ly) << 16);
    lo1 = __half_as_ushort(lz) | ((uint32_t)__half_as_ushort(lw) << 16);
}

// ---------------------------------------------------------------------------
__global__ void init_kernel() {
    int i = blockIdx.x * blockDim.x + threadIdx.x;
    if (i < BNprod * Tdim) {
        g_t2s[i] = INIT_PACK;
        g_s2t[i] = INIT_PACK;
    }
}

// ---------------------------------------------------------------------------
// Kernel 1: fp16x4-split tensor-core GEMM + fused norms + threshold + dual max
// CTA = one 128x128 tile; grid = B*N*4; 256 threads, 8 warps of 64x32 tiles.
// SMEM per stage: As_hi/As_lo/Bs_hi/Bs_lo, each [16 k][128 t] halfs (4 KB),
// 16B units XOR-swizzled by (k&7) for conflict-free STS + ldmatrix.
// ---------------------------------------------------------------------------
#define STG   16384
#define A_HI  0
#define A_LO  4096
#define B_HI  8192
#define B_LO  12288

__global__ __launch_bounds__(256, 1)
void sim_gemm(const float* __restrict__ tar,   // (B, C, T)
              const float* __restrict__ src,   // (B, N, C, T)
              const float* __restrict__ srcm,  // (B, N, T)
              const float* __restrict__ tarm)  // (B, T)
{
    __shared__ __align__(16) char sbuf[2 * STG];
    __shared__ float fA[128], fB[128];
    __shared__ unsigned long long rowp[128], colp[128];

    const int tid  = threadIdx.x;
    const int w    = tid >> 5;
    const int lane = tid & 31;
    const int blk  = blockIdx.x;
    const int bn   = blk >> 2;
    const int sub  = blk & 3;
    const int b    = bn >> 5;
    const int t0   = (sub >> 1) << 7;
    const int s0   = (sub & 1) << 7;

    if (tid < 128) { fA[tid] = 0.f; rowp[tid] = 0ULL; }
    else           { fB[tid - 128] = 0.f; colp[tid - 128] = 0ULL; }

    const uint32_t sb = smem_u32(sbuf);

    // loader addressing: thread handles k = w and k = w+8, t = lane*4..+3
    const float* Ag = tar + (size_t)b  * Cdim * Tdim + (size_t)w * Tdim + t0 + lane * 4;
    const float* Bg = src + (size_t)bn * Cdim * Tdim + (size_t)w * Tdim + s0 + lane * 4;
    const uint32_t stunit = (uint32_t)((lane >> 1) ^ w) * 16 + (lane & 1) * 8;
    const uint32_t st_k0  = (uint32_t)w * 256 + stunit;
    const uint32_t st_k1  = st_k0 + 8 * 256;

    // warp tile: 2(M) x 4(N) -> 64x32
    const int warp_m0 = (w & 1) * 64;
    const int warp_n0 = (w >> 1) * 32;

    // ldmatrix per-lane offsets
    const int krA = (lane & 7) + ((lane >> 4) << 3);
    const int mA8 = ((lane >> 3) & 1) << 3;
    uint32_t aoff[4];
#pragma unroll
    for (int mi = 0; mi < 4; mi++) {
        int mcol = warp_m0 + mi * 16 + mA8;
        aoff[mi] = (uint32_t)krA * 256 + (uint32_t)(((mcol >> 3) ^ (krA & 7)) << 4);
    }
    const int krB = (lane & 7) + (((lane >> 3) & 1) << 3);
    const int nB8 = ((lane >> 4) & 1) << 3;
    uint32_t boff[2];
#pragma unroll
    for (int t2 = 0; t2 < 2; t2++) {
        int ncol = warp_n0 + t2 * 16 + nB8;
        boff[t2] = (uint32_t)krB * 256 + (uint32_t)(((ncol >> 3) ^ (krB & 7)) << 4);
    }

    float acc[4][4][4];
#pragma unroll
    for (int i = 0; i < 4; i++)
#pragma unroll
        for (int j = 0; j < 4; j++)
#pragma unroll
            for (int e = 0; e < 4; e++) acc[i][j][e] = 0.f;

    float sqA[4] = {0.f, 0.f, 0.f, 0.f};
    float sqB[4] = {0.f, 0.f, 0.f, 0.f};

    // prologue: chunk 0
    float4 ra0 = *(const float4*)(Ag);
    float4 ra1 = *(const float4*)(Ag + 8 * Tdim);
    float4 rb0 = *(const float4*)(Bg);
    float4 rb1 = *(const float4*)(Bg + 8 * Tdim);
    {
        uint32_t h0, h1, l0, l1;
        cvt4(ra0, sqA, h0, h1, l0, l1);
        sts64(sb + A_HI + st_k0, h0, h1); sts64(sb + A_LO + st_k0, l0, l1);
        cvt4(ra1, sqA, h0, h1, l0, l1);
        sts64(sb + A_HI + st_k1, h0, h1); sts64(sb + A_LO + st_k1, l0, l1);
        cvt4(rb0, sqB, h0, h1, l0, l1);
        sts64(sb + B_HI + st_k0, h0, h1); sts64(sb + B_LO + st_k0, l0, l1);
        cvt4(rb1, sqB, h0, h1, l0, l1);
        sts64(sb + B_HI + st_k1, h0, h1); sts64(sb + B_LO + st_k1, l0, l1);
    }

    for (int c = 0; c < 48; c++) {
        __syncthreads();
        if (c < 47) {
            const float* Ap = Ag + (size_t)(c + 1) * 16 * Tdim;
            const float* Bp = Bg + (size_t)(c + 1) * 16 * Tdim;
            ra0 = *(const float4*)(Ap);
            ra1 = *(const float4*)(Ap + 8 * Tdim);
            rb0 = *(const float4*)(Bp);
            rb1 = *(const float4*)(Bp + 8 * Tdim);
        }

        const uint32_t base = sb + (c & 1) * STG;
        uint32_t Ah[4][4], Al[4][4], Bh[2][4], Bl[2][4];
#pragma unroll
        for (int mi = 0; mi < 4; mi++) {
            ldm4t(Ah[mi], base + A_HI + aoff[mi]);
            ldm4t(Al[mi], base + A_LO + aoff[mi]);
        }
#pragma unroll
        for (int t2 = 0; t2 < 2; t2++) {
            ldm4t(Bh[t2], base + B_HI + boff[t2]);
            ldm4t(Bl[t2], base + B_LO + boff[t2]);
        }
#pragma unroll
        for (int mi = 0; mi < 4; mi++) {
#pragma unroll
            for (int ni = 0; ni < 4; ni++) {
                const uint32_t* bh = &Bh[ni >> 1][(ni & 1) * 2];
                const uint32_t* bl = &Bl[ni >> 1][(ni & 1) * 2];
                mma16816(acc[mi][ni], Ah[mi], bh);
                mma16816(acc[mi][ni], Ah[mi], bl);
                mma16816(acc[mi][ni], Al[mi], bh);
                mma16816(acc[mi][ni], Al[mi], bl);
            }
        }

        if (c < 47) {
            const uint32_t nb = sb + ((c + 1) & 1) * STG;
            uint32_t h0, h1, l0, l1;
            cvt4(ra0, sqA, h0, h1, l0, l1);
            sts64(nb + A_HI + st_k0, h0, h1); sts64(nb + A_LO + st_k0, l0, l1);
            cvt4(ra1, sqA, h0, h1, l0, l1);
            sts64(nb + A_HI + st_k1, h0, h1); sts64(nb + A_LO + st_k1, l0, l1);
            cvt4(rb0, sqB, h0, h1, l0, l1);
            sts64(nb + B_HI + st_k0, h0, h1); sts64(nb + B_LO + st_k0, l0, l1);
            cvt4(rb1, sqB, h0, h1, l0, l1);
            sts64(nb + B_HI + st_k1, h0, h1); sts64(nb + B_LO + st_k1, l0, l1);
        }
    }
    __syncthreads();

    // fused norms: reduce partial sumsq across the 8 warps
#pragma unroll
    for (int j = 0; j < 4; j++) {
        atomicAdd(&fA[lane * 4 + j], sqA[j]);
        atomicAdd(&fB[lane * 4 + j], sqB[j]);
    }
    __syncthreads();

    if (tid < 128) {
        float inv = 1.0f / fmaxf(sqrtf(fA[tid]), 1e-12f);
        fA[tid] = inv * tarm[b * Tdim + t0 + tid];
    } else {
        int s = tid - 128;
        float inv = 1.0f / fmaxf(sqrtf(fB[s]), 1e-12f);
        fB[s] = inv * srcm[bn * Tdim + s0 + s];
    }
    __syncthreads();

    // epilogue: scale + threshold + packed dual max/argmax
    const int qrow = lane >> 2;
    const int qcol = (lane & 3) * 2;
    unsigned long long rmax[8], cmax[8];
#pragma unroll
    for (int i = 0; i < 8; i++) { rmax[i] = 0ULL; cmax[i] = 0ULL; }

#pragma unroll
    for (int mi = 0; mi < 4; mi++) {
        const int m0l = warp_m0 + mi * 16 + qrow;
        const float fa0 = fA[m0l], fa1 = fA[m0l + 8];
        const int tg0 = t0 + m0l, tg1 = tg0 + 8;
#pragma unroll
        for (int ni = 0; ni < 4; ni++) {
            const int n0l = warp_n0 + ni * 8 + qcol;
            const float fb0 = fB[n0l], fb1 = fB[n0l + 1];
            const int sg0 = s0 + n0l, sg1 = sg0 + 1;
            const float* a = acc[mi][ni];
            float v00 = a[0] * fa0 * fb0; if (v00 < 0.05f) v00 = 0.f;
            float v01 = a[1] * fa0 * fb1; if (v01 < 0.05f) v01 = 0.f;
            float v10 = a[2] * fa1 * fb0; if (v10 < 0.05f) v10 = 0.f;
            float v11 = a[3] * fa1 * fb1; if (v11 < 0.05f) v11 = 0.f;
            rmax[mi * 2 + 0] = umaxll(rmax[mi * 2 + 0],
                                      umaxll(packsi(v00, sg0), packsi(v01, sg1)));
            rmax[mi * 2 + 1] = umaxll(rmax[mi * 2 + 1],
                                      umaxll(packsi(v10, sg0), packsi(v11, sg1)));
            cmax[ni * 2 + 0] = umaxll(cmax[ni * 2 + 0],
                                      umaxll(packsi(v00, tg0), packsi(v10, tg1)));
            cmax[ni * 2 + 1] = umaxll(cmax[ni * 2 + 1],
                                      umaxll(packsi(v01, tg0), packsi(v11, tg1)));
        }
    }
#pragma unroll
    for (int mi = 0; mi < 4; mi++) {
        atomicMax(&rowp[warp_m0 + mi * 16 + qrow],     rmax[mi * 2 + 0]);
        atomicMax(&rowp[warp_m0 + mi * 16 + qrow + 8], rmax[mi * 2 + 1]);
    }
#pragma unroll
    for (int ni = 0; ni < 4; ni++) {
        atomicMax(&colp[warp_n0 + ni * 8 + qcol],     cmax[ni * 2 + 0]);
        atomicMax(&colp[warp_n0 + ni * 8 + qcol + 1], cmax[ni * 2 + 1]);
    }
    __syncthreads();

    if (tid < 128) atomicMax(&g_t2s[bn * Tdim + t0 + tid], rowp[tid]);
    else           atomicMax(&g_s2t[bn * Tdim + s0 + (tid - 128)], colp[tid - 128]);
}

// ---------------------------------------------------------------------------
// Kernel 2: cycle consistency + masks + match_counts + sim_avg
// ---------------------------------------------------------------------------
__global__ void stage2(const float* __restrict__ srcm,
                       const float* __restrict__ tarm,
                       float* __restrict__ out)
{
    const int bn = blockIdx.x;
    const int b  = bn >> 5;
    const int t  = threadIdx.x;

    unsigned long long pt = g_t2s[bn * Tdim + t];
    float sc_t2s = __uint_as_float((unsigned)(pt >> 32));
    int   i_t2s  = (int)(~(unsigned)pt);

    unsigned long long pst = g_s2t[bn * Tdim + t];
    int i_s2t_here = (int)(~(unsigned)pst);

    unsigned long long psi = g_s2t[bn * Tdim + i_t2s];
    float sc_s2t_i = __uint_as_float((unsigned)(psi >> 32));
    int   i_s2s    = (int)(~(unsigned)psi);

    int dx = (i_s2s & 15) - (t & 15);
    int dy = (i_s2s >> 4) - (t >> 4);
    bool cyc  = (dx * dx + dy * dy <= 4) && (sc_s2t_i >= 0.05f);
    bool msim = (sc_t2s >= 0.05f);

    float m = 0.f;
    if (msim && cyc && i_s2t_here != 0 && i_t2s != 0)
        m = tarm[b * Tdim + t] * srcm[bn * Tdim + i_t2s];

    g_mask_all[bn * Tdim + t] = m;

    __shared__ float s1[Tdim], s2[Tdim];
    s1[t] = m;
    s2[t] = sc_t2s * m;
    __syncthreads();
    for (int off = Tdim / 2; off > 0; off >>= 1) {
        if (t < off) { s1[t] += s1[t + off]; s2[t] += s2[t + off]; }
        __syncthreads();
    }
    if (t == 0) {
        float cnt = s1[0];
        out[OFF_CNT + bn] = cnt;
        g_simavg[bn] = (cnt > 0.f) ? (s2[0] * (1.0f / 256.0f)) : 0.f;
    }
}

// ---------------------------------------------------------------------------
// Kernel 3: top-K selection (stable ties) + output formatting
// ---------------------------------------------------------------------------
__global__ void topk_format(float* __restrict__ out)
{
    __shared__ int sel[KTOP];
    const int b = blockIdx.x;
    if (threadIdx.x == 0) {
        float sa[Ndim]; bool used[Ndim];
#pragma unroll
        for (int n = 0; n < Ndim; n++) { sa[n] = g_simavg[b * Ndim + n]; used[n] = false; }
        for (int k = 0; k < KTOP; k++) {
            float best = -1.f; int bi = 0;
            for (int n = 0; n < Ndim; n++)
                if (!used[n] && sa[n] > best) { best = sa[n]; bi = n; }
            used[bi] = true;
            sel[k] = bi;
            out[OFF_ID    + b * KTOP + k] = (float)bi;
            out[OFF_SCORE + b * KTOP + k] = best;
        }
    }
    __syncthreads();
    const int t = threadIdx.x;
#pragma unroll
    for (int k = 0; k < KTOP; k++) {
        const int n   = sel[k];
        const int bk  = b * KTOP + k;
        const int bnT = (b * Ndim + n) * Tdim + t;

        unsigned long long pt = g_t2s[bnT];
        float sc = __uint_as_float((unsigned)(pt >> 32));
        int  idx = (int)(~(unsigned)pt);
        float m  = g_mask_all[bnT];

        out[OFF_SPTS + bk * Tdim + t] = sc;
        const int o = (bk * Tdim + t) * 2;
        if (m != 0.f) {
            out[OFF_TAR + o]     = (float)(t & 15);
            out[OFF_TAR + o + 1] = (float)(t >> 4);
            out[OFF_SRC + o]     = (float)(idx & 15);
            out[OFF_SRC + o + 1] = (float)(idx >> 4);
        } else {
            out[OFF_TAR + o]     = -1.f;
            out[OFF_TAR + o + 1] = -1.f;
            out[OFF_SRC + o]     = -1.f;
            out[OFF_SRC + o + 1] = -1.f;
        }
    }
}

// ---------------------------------------------------------------------------
extern "C" void kernel_launch(void* const* d_in, const int* in_sizes, int n_in,
                              void* d_out, int out_size)
{
    const float* src  = (const float*)d_in[0];
    const float* tar  = (const float*)d_in[1];
    const float* srcm = (const float*)d_in[2];
    const float* tarm = (const float*)d_in[3];
    float* out = (float*)d_out;

    init_kernel<<<BNprod * Tdim / 256, 256>>>();
    sim_gemm<<<BNprod * 4, 256>>>(tar, src, srcm, tarm);
    stage2<<<BNprod, Tdim>>>(srcm, tarm, out);
    topk_format<<<Bdim, 256>>>(out);
}

// round 7
// speedup vs baseline: 1.7667x; 1.0376x over previous
#include <cuda_runtime.h>
#include <cuda_fp16.h>
#include <cstdint>

#define Bdim   8
#define Ndim   32
#define Cdim   768
#define Tdim   256
#define KTOP   5
#define BNprod (Bdim * Ndim)

// Output layout (float32, concatenated in return-tuple order)
#define OFF_ID      0
#define OFF_SCORE   40
#define OFF_SPTS    80
#define OFF_TAR     10320
#define OFF_SRC     30800
#define OFF_CNT     51280

// ---------------- global scratch ----------------
__device__ unsigned long long g_t2s[BNprod * Tdim];
__device__ unsigned long long g_s2t[BNprod * Tdim];
__device__ float              g_mask_all[BNprod * Tdim];
__device__ float              g_simavg[BNprod];

__device__ __half g_AH[(size_t)Bdim   * Cdim * Tdim];   // tar hi
__device__ __half g_AL[(size_t)Bdim   * Cdim * Tdim];   // tar lo
__device__ __half g_BH[(size_t)BNprod * Cdim * Tdim];   // src hi (100MB)
__device__ __half g_BL[(size_t)BNprod * Cdim * Tdim];   // src lo (100MB)
__device__ float  g_fT[Bdim * Tdim];                    // inv_norm * tar_mask
__device__ float  g_fS[BNprod * Tdim];                  // inv_norm * src_mask

#define INIT_PACK 0x00000000FFFFFFFFULL

static __device__ __forceinline__ unsigned long long packsi(float score, int idx) {
    return ((unsigned long long)__float_as_uint(score) << 32) |
           (unsigned long long)(unsigned)(~idx);
}
static __device__ __forceinline__ unsigned long long umaxll(unsigned long long a,
                                                            unsigned long long b) {
    return a > b ? a : b;
}
static __device__ __forceinline__ uint32_t smem_u32(const void* p) {
    uint32_t a;
    asm("{ .reg .u64 t; cvta.to.shared.u64 t, %1; cvt.u32.u64 %0, t; }" : "=r"(a) : "l"(p));
    return a;
}
static __device__ __forceinline__ void ldm4t(uint32_t* r, uint32_t addr) {
    asm volatile("ldmatrix.sync.aligned.m8n8.x4.trans.shared.b16 {%0,%1,%2,%3}, [%4];"
                 : "=r"(r[0]), "=r"(r[1]), "=r"(r[2]), "=r"(r[3]) : "r"(addr));
}
static __device__ __forceinline__ void mma16816(float* d, const uint32_t* a,
                                                const uint32_t* b) {
    asm volatile(
        "mma.sync.aligned.m16n8k16.row.col.f32.f16.f16.f32 "
        "{%0,%1,%2,%3}, {%4,%5,%6,%7}, {%8,%9}, {%0,%1,%2,%3};"
        : "+f"(d[0]), "+f"(d[1]), "+f"(d[2]), "+f"(d[3])
        : "r"(a[0]), "r"(a[1]), "r"(a[2]), "r"(a[3]), "r"(b[0]), "r"(b[1]));
}
static __device__ __forceinline__ void cpasync16(uint32_t dst, const void* src) {
    asm volatile("cp.async.cg.shared.global [%0], [%1], 16;" :: "r"(dst), "l"(src)
                 : "memory");
}
#define CP_COMMIT()  asm volatile("cp.async.commit_group;" ::: "memory")
#define CP_WAIT(n)   asm volatile("cp.async.wait_group %0;" :: "n"(n) : "memory")

// ---------------------------------------------------------------------------
__global__ void init_kernel() {
    int i = blockIdx.x * blockDim.x + threadIdx.x;
    if (i < BNprod * Tdim) {
        g_t2s[i] = INIT_PACK;
        g_s2t[i] = INIT_PACK;
    }
}

// ---------------------------------------------------------------------------
// Kernel A: one-shot fp32 -> fp16 hi/lo conversion + exact column norms.
// blocks [0, BNprod): src slab bn; blocks [BNprod, BNprod+Bdim): tar slab b.
// thread = one t-column; sequential fp32 sumsq matches reference exactly.
// ---------------------------------------------------------------------------
__global__ __launch_bounds__(256)
void conv_kernel(const float* __restrict__ src, const float* __restrict__ tar,
                 const float* __restrict__ srcm, const float* __restrict__ tarm)
{
    const int blk = blockIdx.x;
    const int t   = threadIdx.x;

    const float* p;
    __half *ph, *pl;
    if (blk < BNprod) {
        p  = src  + (size_t)blk * Cdim * Tdim + t;
        ph = g_BH + (size_t)blk * Cdim * Tdim + t;
        pl = g_BL + (size_t)blk * Cdim * Tdim + t;
    } else {
        const int b = blk - BNprod;
        p  = tar  + (size_t)b * Cdim * Tdim + t;
        ph = g_AH + (size_t)b * Cdim * Tdim + t;
        pl = g_AL + (size_t)b * Cdim * Tdim + t;
    }

    float sq = 0.f;
#pragma unroll 4
    for (int c = 0; c < Cdim; c++) {
        float x = __ldg(p + (size_t)c * Tdim);
        sq = fmaf(x, x, sq);
        __half h = __float2half_rn(x);
        __half l = __float2half_rn(x - __half2float(h));
        ph[(size_t)c * Tdim] = h;
        pl[(size_t)c * Tdim] = l;
    }
    float inv = 1.0f / fmaxf(sqrtf(sq), 1e-12f);
    if (blk < BNprod)
        g_fS[blk * Tdim + t] = inv * srcm[blk * Tdim + t];
    else
        g_fT[(blk - BNprod) * Tdim + t] = inv * tarm[(blk - BNprod) * Tdim + t];
}

// ---------------------------------------------------------------------------
// Kernel B: lean tensor-core GEMM (3-product fp16 split) + threshold + dual max
// CTA = one 128x128 tile; grid = B*N*4; 256 threads, 8 warps of 64x32 tiles.
// SMEM stage (16KB): 4 planes [16 k][128 t] halfs, 16B units XOR-swizzled by k&7.
// 3-stage cp.async pipeline.
// ---------------------------------------------------------------------------
#define STG   16384
#define A_HI  0
#define A_LO  4096
#define B_HI  8192
#define B_LO  12288

__global__ __launch_bounds__(256, 1)
void sim_gemm()
{
    __shared__ __align__(1024) char sbuf[3 * STG];
    __shared__ float fA[128], fB[128];
    __shared__ unsigned long long rowp[128], colp[128];

    const int tid  = threadIdx.x;
    const int w    = tid >> 5;
    const int lane = tid & 31;
    const int blk  = blockIdx.x;
    const int bn   = blk >> 2;
    const int sub  = blk & 3;
    const int b    = bn >> 5;
    const int t0   = (sub >> 1) << 7;
    const int s0   = (sub & 1) << 7;

    if (tid < 128) {
        fA[tid] = g_fT[b * Tdim + t0 + tid];
        rowp[tid] = 0ULL;
    } else {
        fB[tid - 128] = g_fS[bn * Tdim + s0 + (tid - 128)];
        colp[tid - 128] = 0ULL;
    }

    const uint32_t sb = smem_u32(sbuf);

    // cp.async addressing: thread -> (k = tid>>4, u = tid&15), one 16B unit/plane
    const int kk = tid >> 4;
    const int uu = tid & 15;
    const uint32_t dst_off = (uint32_t)kk * 256 + (uint32_t)((uu ^ (kk & 7)) << 4);

    const size_t gstep = (size_t)16 * Tdim;
    const __half* gAh = g_AH + (size_t)b  * Cdim * Tdim + (size_t)kk * Tdim + t0 + uu * 8;
    const __half* gAl = g_AL + (size_t)b  * Cdim * Tdim + (size_t)kk * Tdim + t0 + uu * 8;
    const __half* gBh = g_BH + (size_t)bn * Cdim * Tdim + (size_t)kk * Tdim + s0 + uu * 8;
    const __half* gBl = g_BL + (size_t)bn * Cdim * Tdim + (size_t)kk * Tdim + s0 + uu * 8;

    // warp tile: 2(M) x 4(N) -> 64x32
    const int warp_m0 = (w & 1) * 64;
    const int warp_n0 = (w >> 1) * 32;

    // ldmatrix per-lane offsets (identical layout to R5)
    const int krA = (lane & 7) + ((lane >> 4) << 3);
    const int mA8 = ((lane >> 3) & 1) << 3;
    uint32_t aoff[4];
#pragma unroll
    for (int mi = 0; mi < 4; mi++) {
        int mcol = warp_m0 + mi * 16 + mA8;
        aoff[mi] = (uint32_t)krA * 256 + (uint32_t)(((mcol >> 3) ^ (krA & 7)) << 4);
    }
    const int krB = (lane & 7) + (((lane >> 3) & 1) << 3);
    const int nB8 = ((lane >> 4) & 1) << 3;
    uint32_t boff[2];
#pragma unroll
    for (int t2 = 0; t2 < 2; t2++) {
        int ncol = warp_n0 + t2 * 16 + nB8;
        boff[t2] = (uint32_t)krB * 256 + (uint32_t)(((ncol >> 3) ^ (krB & 7)) << 4);
    }

    float acc[4][4][4];
#pragma unroll
    for (int i = 0; i < 4; i++)
#pragma unroll
        for (int j = 0; j < 4; j++)
#pragma unroll
            for (int e = 0; e < 4; e++) acc[i][j][e] = 0.f;

    // prologue: prefetch stages 0, 1
#pragma unroll
    for (int pc = 0; pc < 2; pc++) {
        const uint32_t base = sb + pc * STG + dst_off;
        cpasync16(base + A_HI, gAh + pc * gstep);
        cpasync16(base + A_LO, gAl + pc * gstep);
        cpasync16(base + B_HI, gBh + pc * gstep);
        cpasync16(base + B_LO, gBl + pc * gstep);
        CP_COMMIT();
    }

    int stage = 0;
    for (int c = 0; c < 48; c++) {
        if (c < 46) { CP_WAIT(1); } else { CP_WAIT(0); }
        __syncthreads();

        const uint32_t base = sb + stage * STG;
        uint32_t Bh[2][4], Bl[2][4];
#pragma unroll
        for (int t2 = 0; t2 < 2; t2++) {
            ldm4t(Bh[t2], base + B_HI + boff[t2]);
            ldm4t(Bl[t2], base + B_LO + boff[t2]);
        }
#pragma unroll
        for (int mi = 0; mi < 4; mi++) {
            uint32_t Ah[4], Al[4];
            ldm4t(Ah, base + A_HI + aoff[mi]);
            ldm4t(Al, base + A_LO + aoff[mi]);
#pragma unroll
            for (int ni = 0; ni < 4; ni++) {
                const uint32_t* bh = &Bh[ni >> 1][(ni & 1) * 2];
                const uint32_t* bl = &Bl[ni >> 1][(ni & 1) * 2];
                mma16816(acc[mi][ni], Ah, bh);
                mma16816(acc[mi][ni], Ah, bl);
                mma16816(acc[mi][ni], Al, bh);
            }
        }

        if (c + 2 < 48) {
            int ps = stage + 2;              // (stage + 2) % 3  -- FIXED
            if (ps >= 3) ps -= 3;
            const uint32_t nb = sb + (uint32_t)ps * STG + dst_off;
            const size_t go = (size_t)(c + 2) * gstep;
            cpasync16(nb + A_HI, gAh + go);
            cpasync16(nb + A_LO, gAl + go);
            cpasync16(nb + B_HI, gBh + go);
            cpasync16(nb + B_LO, gBl + go);
            CP_COMMIT();
        }
        stage = (stage + 1 == 3) ? 0 : stage + 1;
    }
    __syncthreads();

    // epilogue: scale + threshold + packed dual max/argmax
    const int qrow = lane >> 2;
    const int qcol = (lane & 3) * 2;
    unsigned long long rmax[8], cmax[8];
#pragma unroll
    for (int i = 0; i < 8; i++) { rmax[i] = 0ULL; cmax[i] = 0ULL; }

#pragma unroll
    for (int mi = 0; mi < 4; mi++) {
        const int m0l = warp_m0 + mi * 16 + qrow;
        const float fa0 = fA[m0l], fa1 = fA[m0l + 8];
        const int tg0 = t0 + m0l, tg1 = tg0 + 8;
#pragma unroll
        for (int ni = 0; ni < 4; ni++) {
            const int n0l = warp_n0 + ni * 8 + qcol;
            const float fb0 = fB[n0l], fb1 = fB[n0l + 1];
            const int sg0 = s0 + n0l, sg1 = sg0 + 1;
            const float* a = acc[mi][ni];
            float v00 = a[0] * fa0 * fb0; if (v00 < 0.05f) v00 = 0.f;
            float v01 = a[1] * fa0 * fb1; if (v01 < 0.05f) v01 = 0.f;
            float v10 = a[2] * fa1 * fb0; if (v10 < 0.05f) v10 = 0.f;
            float v11 = a[3] * fa1 * fb1; if (v11 < 0.05f) v11 = 0.f;
            rmax[mi * 2 + 0] = umaxll(rmax[mi * 2 + 0],
                                      umaxll(packsi(v00, sg0), packsi(v01, sg1)));
            rmax[mi * 2 + 1] = umaxll(rmax[mi * 2 + 1],
                                      umaxll(packsi(v10, sg0), packsi(v11, sg1)));
            cmax[ni * 2 + 0] = umaxll(cmax[ni * 2 + 0],
                                      umaxll(packsi(v00, tg0), packsi(v10, tg1)));
            cmax[ni * 2 + 1] = umaxll(cmax[ni * 2 + 1],
                                      umaxll(packsi(v01, tg0), packsi(v11, tg1)));
        }
    }
#pragma unroll
    for (int mi = 0; mi < 4; mi++) {
        atomicMax(&rowp[warp_m0 + mi * 16 + qrow],     rmax[mi * 2 + 0]);
        atomicMax(&rowp[warp_m0 + mi * 16 + qrow + 8], rmax[mi * 2 + 1]);
    }
#pragma unroll
    for (int ni = 0; ni < 4; ni++) {
        atomicMax(&colp[warp_n0 + ni * 8 + qcol],     cmax[ni * 2 + 0]);
        atomicMax(&colp[warp_n0 + ni * 8 + qcol + 1], cmax[ni * 2 + 1]);
    }
    __syncthreads();

    if (tid < 128) atomicMax(&g_t2s[bn * Tdim + t0 + tid], rowp[tid]);
    else           atomicMax(&g_s2t[bn * Tdim + s0 + (tid - 128)], colp[tid - 128]);
}

// ---------------------------------------------------------------------------
// Kernel C: cycle consistency + masks + match_counts + sim_avg
// ---------------------------------------------------------------------------
__global__ void stage2(const float* __restrict__ srcm,
                       const float* __restrict__ tarm,
                       float* __restrict__ out)
{
    const int bn = blockIdx.x;
    const int b  = bn >> 5;
    const int t  = threadIdx.x;

    unsigned long long pt = g_t2s[bn * Tdim + t];
    float sc_t2s = __uint_as_float((unsigned)(pt >> 32));
    int   i_t2s  = (int)(~(unsigned)pt);

    unsigned long long pst = g_s2t[bn * Tdim + t];
    int i_s2t_here = (int)(~(unsigned)pst);

    unsigned long long psi = g_s2t[bn * Tdim + i_t2s];
    float sc_s2t_i = __uint_as_float((unsigned)(psi >> 32));
    int   i_s2s    = (int)(~(unsigned)psi);

    int dx = (i_s2s & 15) - (t & 15);
    int dy = (i_s2s >> 4) - (t >> 4);
    bool cyc  = (dx * dx + dy * dy <= 4) && (sc_s2t_i >= 0.05f);
    bool msim = (sc_t2s >= 0.05f);

    float m = 0.f;
    if (msim && cyc && i_s2t_here != 0 && i_t2s != 0)
        m = tarm[b * Tdim + t] * srcm[bn * Tdim + i_t2s];

    g_mask_all[bn * Tdim + t] = m;

    __shared__ float s1[Tdim], s2[Tdim];
    s1[t] = m;
    s2[t] = sc_t2s * m;
    __syncthreads();
    for (int off = Tdim / 2; off > 0; off >>= 1) {
        if (t < off) { s1[t] += s1[t + off]; s2[t] += s2[t + off]; }
        __syncthreads();
    }
    if (t == 0) {
        float cnt = s1[0];
        out[OFF_CNT + bn] = cnt;
        g_simavg[bn] = (cnt > 0.f) ? (s2[0] * (1.0f / 256.0f)) : 0.f;
    }
}

// ---------------------------------------------------------------------------
// Kernel D: top-K selection (stable ties) + output formatting
// ---------------------------------------------------------------------------
__global__ void topk_format(float* __restrict__ out)
{
    __shared__ int sel[KTOP];
    const int b = blockIdx.x;
    if (threadIdx.x == 0) {
        float sa[Ndim]; bool used[Ndim];
#pragma unroll
        for (int n = 0; n < Ndim; n++) { sa[n] = g_simavg[b * Ndim + n]; used[n] = false; }
        for (int k = 0; k < KTOP; k++) {
            float best = -1.f; int bi = 0;
            for (int n = 0; n < Ndim; n++)
                if (!used[n] && sa[n] > best) { best = sa[n]; bi = n; }
            used[bi] = true;
            sel[k] = bi;
            out[OFF_ID    + b * KTOP + k] = (float)bi;
            out[OFF_SCORE + b * KTOP + k] = best;
        }
    }
    __syncthreads();
    const int t = threadIdx.x;
#pragma unroll
    for (int k = 0; k < KTOP; k++) {
        const int n   = sel[k];
        const int bk  = b * KTOP + k;
        const int bnT = (b * Ndim + n) * Tdim + t;

        unsigned long long pt = g_t2s[bnT];
        float sc = __uint_as_float((unsigned)(pt >> 32));
        int  idx = (int)(~(unsigned)pt);
        float m  = g_mask_all[bnT];

        out[OFF_SPTS + bk * Tdim + t] = sc;
        const int o = (bk * Tdim + t) * 2;
        if (m != 0.f) {
            out[OFF_TAR + o]     = (float)(t & 15);
            out[OFF_TAR + o + 1] = (float)(t >> 4);
            out[OFF_SRC + o]     = (float)(idx & 15);
            out[OFF_SRC + o + 1] = (float)(idx >> 4);
        } else {
            out[OFF_TAR + o]     = -1.f;
            out[OFF_TAR + o + 1] = -1.f;
            out[OFF_SRC + o]     = -1.f;
            out[OFF_SRC + o + 1] = -1.f;
        }
    }
}

// ---------------------------------------------------------------------------
extern "C" void kernel_launch(void* const* d_in, const int* in_sizes, int n_in,
                              void* d_out, int out_size)
{
    const float* src  = (const float*)d_in[0];
    const float* tar  = (const float*)d_in[1];
    const float* srcm = (const float*)d_in[2];
    const float* tarm = (const float*)d_in[3];
    float* out = (float*)d_out;

    init_kernel<<<BNprod * Tdim / 256, 256>>>();
    conv_kernel<<<BNprod + Bdim, 256>>>(src, tar, srcm, tarm);
    sim_gemm<<<BNprod * 4, 256>>>();
    stage2<<<BNprod, Tdim>>>(srcm, tarm, out);
    topk_format<<<Bdim, 256>>>(out);
}

// round 8
// speedup vs baseline: 2.0565x; 1.1641x over previous
#include <cuda_runtime.h>
#include <cuda_fp16.h>
#include <cstdint>

#define Bdim   8
#define Ndim   32
#define Cdim   768
#define Tdim   256
#define KTOP   5
#define BNprod (Bdim * Ndim)

// Output layout (float32, concatenated in return-tuple order)
#define OFF_ID      0
#define OFF_SCORE   40
#define OFF_SPTS    80
#define OFF_TAR     10320
#define OFF_SRC     30800
#define OFF_CNT     51280

// ---------------- global scratch ----------------
__device__ unsigned long long g_t2sA[BNprod * Tdim];   // row max, s-half 0
__device__ unsigned long long g_t2sB[BNprod * Tdim];   // row max, s-half 1
__device__ unsigned long long g_s2t[BNprod * Tdim];    // col max (complete)
__device__ float              g_mask_all[BNprod * Tdim];
__device__ float              g_simavg[BNprod];

__device__ __half g_AH[(size_t)Bdim * Cdim * Tdim];    // tar hi (3.1MB)
__device__ __half g_AL[(size_t)Bdim * Cdim * Tdim];    // tar lo
__device__ float  g_fT[Bdim * Tdim];                   // inv_norm * tar_mask

static __device__ __forceinline__ unsigned long long packsi(float score, int idx) {
    return ((unsigned long long)__float_as_uint(score) << 32) |
           (unsigned long long)(unsigned)(~idx);
}
static __device__ __forceinline__ unsigned long long umaxll(unsigned long long a,
                                                            unsigned long long b) {
    return a > b ? a : b;
}
static __device__ __forceinline__ uint32_t smem_u32(const void* p) {
    uint32_t a;
    asm("{ .reg .u64 t; cvta.to.shared.u64 t, %1; cvt.u32.u64 %0, t; }" : "=r"(a) : "l"(p));
    return a;
}
static __device__ __forceinline__ void ldm4t(uint32_t* r, uint32_t addr) {
    asm volatile("ldmatrix.sync.aligned.m8n8.x4.trans.shared.b16 {%0,%1,%2,%3}, [%4];"
                 : "=r"(r[0]), "=r"(r[1]), "=r"(r[2]), "=r"(r[3]) : "r"(addr));
}
static __device__ __forceinline__ void mma16816(float* d, const uint32_t* a,
                                                const uint32_t* b) {
    asm volatile(
        "mma.sync.aligned.m16n8k16.row.col.f32.f16.f16.f32 "
        "{%0,%1,%2,%3}, {%4,%5,%6,%7}, {%8,%9}, {%0,%1,%2,%3};"
        : "+f"(d[0]), "+f"(d[1]), "+f"(d[2]), "+f"(d[3])
        : "r"(a[0]), "r"(a[1]), "r"(a[2]), "r"(a[3]), "r"(b[0]), "r"(b[1]));
}
static __device__ __forceinline__ void cpasync16(uint32_t dst, const void* src) {
    asm volatile("cp.async.cg.shared.global [%0], [%1], 16;" :: "r"(dst), "l"(src)
                 : "memory");
}
#define CP_COMMIT()  asm volatile("cp.async.commit_group;" ::: "memory")
#define CP_WAIT(n)   asm volatile("cp.async.wait_group %0;" :: "n"(n) : "memory")

static __device__ __forceinline__ void sts64(uint32_t addr, uint32_t r0, uint32_t r1) {
    asm volatile("st.shared.v2.b32 [%0], {%1, %2};" :: "r"(addr), "r"(r0), "r"(r1)
                 : "memory");
}
// float4 -> packed fp16 hi/lo pairs, accumulate sumsq
static __device__ __forceinline__ void cvt4(float4 v, float* sq,
                                            uint32_t& hi0, uint32_t& hi1,
                                            uint32_t& lo0, uint32_t& lo1) {
    sq[0] = fmaf(v.x, v.x, sq[0]);
    sq[1] = fmaf(v.y, v.y, sq[1]);
    sq[2] = fmaf(v.z, v.z, sq[2]);
    sq[3] = fmaf(v.w, v.w, sq[3]);
    __half hx = __float2half_rn(v.x), hy = __float2half_rn(v.y);
    __half hz = __float2half_rn(v.z), hw = __float2half_rn(v.w);
    __half lx = __float2half_rn(v.x - __half2float(hx));
    __half ly = __float2half_rn(v.y - __half2float(hy));
    __half lz = __float2half_rn(v.z - __half2float(hz));
    __half lw = __float2half_rn(v.w - __half2float(hw));
    hi0 = __half_as_ushort(hx) | ((uint32_t)__half_as_ushort(hy) << 16);
    hi1 = __half_as_ushort(hz) | ((uint32_t)__half_as_ushort(hw) << 16);
    lo0 = __half_as_ushort(lx) | ((uint32_t)__half_as_ushort(ly) << 16);
    lo1 = __half_as_ushort(lz) | ((uint32_t)__half_as_ushort(lw) << 16);
}

// ---------------------------------------------------------------------------
// Kernel A: tar fp32 -> fp16 hi/lo planes + exact tar norms (tiny: 8 blocks)
// ---------------------------------------------------------------------------
__global__ __launch_bounds__(256)
void conv_tar(const float* __restrict__ tar, const float* __restrict__ tarm)
{
    const int b = blockIdx.x;
    const int t = threadIdx.x;
    const float* p  = tar  + (size_t)b * Cdim * Tdim + t;
    __half* ph = g_AH + (size_t)b * Cdim * Tdim + t;
    __half* pl = g_AL + (size_t)b * Cdim * Tdim + t;

    float sq = 0.f;
#pragma unroll 8
    for (int c = 0; c < Cdim; c++) {
        float x = __ldg(p + (size_t)c * Tdim);
        sq = fmaf(x, x, sq);
        __half h = __float2half_rn(x);
        __half l = __float2half_rn(x - __half2float(h));
        ph[(size_t)c * Tdim] = h;
        pl[(size_t)c * Tdim] = l;
    }
    float inv = 1.0f / fmaxf(sqrtf(sq), 1e-12f);
    g_fT[b * Tdim + t] = inv * tarm[b * Tdim + t];
}

// ---------------------------------------------------------------------------
// Kernel B: M=256 x N=128 fused GEMM. B (src) loaded fp32, converted in-kernel
// (each element exactly once), sumsq fused. 512 threads, 16 warps of 64x32.
// A planes: 3-stage cp.async (16KB/stage). B planes: LDG->cvt->STS, 2-buffer.
// ---------------------------------------------------------------------------
#define ASTG      16384     // A stage: A_HI 8KB + A_LO 8KB
#define BBUF_BASE 49152
#define BBUF      8192      // B buf: B_HI 4KB + B_LO 4KB
#define DYN_SMEM  65536

__global__ __launch_bounds__(512)
void sim_gemm(const float* __restrict__ src, const float* __restrict__ srcm)
{
    extern __shared__ char dsm[];
    __shared__ float fA[256], fB[128], fBsq[128];
    __shared__ unsigned long long rowp[256], colp[128];

    const uint32_t sb = smem_u32(dsm);
    const int tid  = threadIdx.x;
    const int w    = tid >> 5;
    const int lane = tid & 31;
    const int blk  = blockIdx.x;
    const int bn   = blk >> 1;
    const int sh   = blk & 1;
    const int s0   = sh << 7;
    const int b    = bn >> 5;

    if (tid < 256) { fA[tid] = g_fT[b * Tdim + tid]; rowp[tid] = 0ULL; }
    if (tid < 128) { fBsq[tid] = 0.f; colp[tid] = 0ULL; }

    // A cp.async mapping: k-row = w, 16B unit = lane
    const int ka = w, ua = lane;
    const __half* gAh = g_AH + (size_t)b * Cdim * Tdim + (size_t)ka * Tdim + ua * 8;
    const __half* gAl = g_AL + (size_t)b * Cdim * Tdim + (size_t)ka * Tdim + ua * 8;
    const uint32_t adst = (uint32_t)ka * 512 + (uint32_t)((ua ^ (ka & 7)) << 4);
    const size_t gstep_h = (size_t)16 * Tdim;

    // B ldg/sts mapping: k-row = w, 4 floats at s = q*4
    const int q = lane;
    const float* gB = src + (size_t)bn * Cdim * Tdim + (size_t)ka * Tdim + s0 + q * 4;
    const uint32_t bsts = (uint32_t)ka * 256 +
                          (uint32_t)((((q >> 1) ^ (ka & 7))) << 4) + (q & 1) * 8;

    // warp tile
    const int wm = w & 3;         // m group of 64
    const int wn = w >> 2;        // n group of 32
    const int warp_m0 = wm * 64;
    const int warp_n0 = wn * 32;

    // ldmatrix per-lane offsets (A plane row = 512B, B plane row = 256B)
    const int krA = (lane & 7) + ((lane >> 4) << 3);
    const int mA8 = ((lane >> 3) & 1) << 3;
    uint32_t aoff[4];
#pragma unroll
    for (int mi = 0; mi < 4; mi++) {
        int mcol = warp_m0 + mi * 16 + mA8;
        aoff[mi] = (uint32_t)krA * 512 + (uint32_t)(((mcol >> 3) ^ (krA & 7)) << 4);
    }
    const int krB = (lane & 7) + (((lane >> 3) & 1) << 3);
    const int nB8 = ((lane >> 4) & 1) << 3;
    uint32_t boff[2];
#pragma unroll
    for (int t2 = 0; t2 < 2; t2++) {
        int ncol = warp_n0 + t2 * 16 + nB8;
        boff[t2] = (uint32_t)krB * 256 + (uint32_t)(((ncol >> 3) ^ (krB & 7)) << 4);
    }

    float acc[4][4][4];
#pragma unroll
    for (int i = 0; i < 4; i++)
#pragma unroll
        for (int j = 0; j < 4; j++)
#pragma unroll
            for (int e = 0; e < 4; e++) acc[i][j][e] = 0.f;

    float sq[4] = {0.f, 0.f, 0.f, 0.f};

    // prologue: A stages 0,1 in flight; B chunk 0 in regs
#pragma unroll
    for (int pc = 0; pc < 2; pc++) {
        const uint32_t ab = sb + pc * ASTG;
        cpasync16(ab + adst,        gAh + pc * gstep_h);
        cpasync16(ab + 8192 + adst, gAl + pc * gstep_h);
        CP_COMMIT();
    }
    float4 rb = *(const float4*)gB;

    int stage = 0;
    for (int c = 0; c < 48; c++) {
        uint32_t h0, h1, l0, l1;
        cvt4(rb, sq, h0, h1, l0, l1);
        const uint32_t bb = sb + BBUF_BASE + (uint32_t)(c & 1) * BBUF;
        sts64(bb + bsts,        h0, h1);
        sts64(bb + 4096 + bsts, l0, l1);
        if (c < 47) rb = *(const float4*)(gB + (size_t)(c + 1) * gstep_h);

        if (c < 46) { CP_WAIT(1); } else { CP_WAIT(0); }
        __syncthreads();

        const uint32_t abase = sb + (uint32_t)stage * ASTG;
        uint32_t Bh[2][4], Bl[2][4];
#pragma unroll
        for (int t2 = 0; t2 < 2; t2++) {
            ldm4t(Bh[t2], bb + boff[t2]);
            ldm4t(Bl[t2], bb + 4096 + boff[t2]);
        }
#pragma unroll
        for (int mi = 0; mi < 4; mi++) {
            uint32_t Ah[4], Al[4];
            ldm4t(Ah, abase + aoff[mi]);
            ldm4t(Al, abase + 8192 + aoff[mi]);
#pragma unroll
            for (int ni = 0; ni < 4; ni++) {
                const uint32_t* bh = &Bh[ni >> 1][(ni & 1) * 2];
                const uint32_t* bl = &Bl[ni >> 1][(ni & 1) * 2];
                mma16816(acc[mi][ni], Ah, bh);
                mma16816(acc[mi][ni], Ah, bl);
                mma16816(acc[mi][ni], Al, bh);
            }
        }

        if (c + 2 < 48) {
            int ps = stage + 2;
            if (ps >= 3) ps -= 3;
            const uint32_t nb = sb + (uint32_t)ps * ASTG;
            cpasync16(nb + adst,        gAh + (size_t)(c + 2) * gstep_h);
            cpasync16(nb + 8192 + adst, gAl + (size_t)(c + 2) * gstep_h);
            CP_COMMIT();
        }
        stage = (stage + 1 == 3) ? 0 : stage + 1;
    }

    // src norms: merge per-thread partials, then fold in mask
#pragma unroll
    for (int j = 0; j < 4; j++) atomicAdd(&fBsq[q * 4 + j], sq[j]);
    __syncthreads();
    if (tid < 128) {
        float inv = 1.0f / fmaxf(sqrtf(fBsq[tid]), 1e-12f);
        fB[tid] = inv * srcm[bn * Tdim + s0 + tid];
    }
    __syncthreads();

    // epilogue: scale + threshold + packed dual max/argmax
    const int qrow = lane >> 2;
    const int qcol = (lane & 3) * 2;
    unsigned long long rmax[8], cmax[8];
#pragma unroll
    for (int i = 0; i < 8; i++) { rmax[i] = 0ULL; cmax[i] = 0ULL; }

#pragma unroll
    for (int mi = 0; mi < 4; mi++) {
        const int m0l = warp_m0 + mi * 16 + qrow;     // global t (M covers all 256)
        const float fa0 = fA[m0l], fa1 = fA[m0l + 8];
        const int tg0 = m0l, tg1 = m0l + 8;
#pragma unroll
        for (int ni = 0; ni < 4; ni++) {
            const int n0l = warp_n0 + ni * 8 + qcol;
            const float fb0 = fB[n0l], fb1 = fB[n0l + 1];
            const int sg0 = s0 + n0l, sg1 = sg0 + 1;
            const float* a = acc[mi][ni];
            float v00 = a[0] * fa0 * fb0; if (v00 < 0.05f) v00 = 0.f;
            float v01 = a[1] * fa0 * fb1; if (v01 < 0.05f) v01 = 0.f;
            float v10 = a[2] * fa1 * fb0; if (v10 < 0.05f) v10 = 0.f;
            float v11 = a[3] * fa1 * fb1; if (v11 < 0.05f) v11 = 0.f;
            rmax[mi * 2 + 0] = umaxll(rmax[mi * 2 + 0],
                                      umaxll(packsi(v00, sg0), packsi(v01, sg1)));
            rmax[mi * 2 + 1] = umaxll(rmax[mi * 2 + 1],
                                      umaxll(packsi(v10, sg0), packsi(v11, sg1)));
            cmax[ni * 2 + 0] = umaxll(cmax[ni * 2 + 0],
                                      umaxll(packsi(v00, tg0), packsi(v10, tg1)));
            cmax[ni * 2 + 1] = umaxll(cmax[ni * 2 + 1],
                                      umaxll(packsi(v01, tg0), packsi(v11, tg1)));
        }
    }
#pragma unroll
    for (int mi = 0; mi < 4; mi++) {
        atomicMax(&rowp[warp_m0 + mi * 16 + qrow],     rmax[mi * 2 + 0]);
        atomicMax(&rowp[warp_m0 + mi * 16 + qrow + 8], rmax[mi * 2 + 1]);
    }
#pragma unroll
    for (int ni = 0; ni < 4; ni++) {
        atomicMax(&colp[warp_n0 + ni * 8 + qcol],     cmax[ni * 2 + 0]);
        atomicMax(&colp[warp_n0 + ni * 8 + qcol + 1], cmax[ni * 2 + 1]);
    }
    __syncthreads();

    // direct stores: no global atomics, no init kernel
    if (tid < 256) {
        if (sh == 0) g_t2sA[bn * Tdim + tid] = rowp[tid];
        else         g_t2sB[bn * Tdim + tid] = rowp[tid];
    } else if (tid < 384) {
        g_s2t[bn * Tdim + s0 + (tid - 256)] = colp[tid - 256];
    }
}

// ---------------------------------------------------------------------------
// Kernel C: merge row halves + cycle consistency + counts + sim_avg
// ---------------------------------------------------------------------------
__global__ void stage2(const float* __restrict__ srcm,
                       const float* __restrict__ tarm,
                       float* __restrict__ out)
{
    const int bn = blockIdx.x;
    const int b  = bn >> 5;
    const int t  = threadIdx.x;

    unsigned long long pt = umaxll(g_t2sA[bn * Tdim + t], g_t2sB[bn * Tdim + t]);
    g_t2sA[bn * Tdim + t] = pt;                       // combined, for topk
    float sc_t2s = __uint_as_float((unsigned)(pt >> 32));
    int   i_t2s  = (int)(~(unsigned)pt);

    int i_s2t_here = (int)(~(unsigned)g_s2t[bn * Tdim + t]);

    unsigned long long psi = g_s2t[bn * Tdim + i_t2s];
    float sc_s2t_i = __uint_as_float((unsigned)(psi >> 32));
    int   i_s2s    = (int)(~(unsigned)psi);

    int dx = (i_s2s & 15) - (t & 15);
    int dy = (i_s2s >> 4) - (t >> 4);
    bool cyc  = (dx * dx + dy * dy <= 4) && (sc_s2t_i >= 0.05f);
    bool msim = (sc_t2s >= 0.05f);

    float m = 0.f;
    if (msim && cyc && i_s2t_here != 0 && i_t2s != 0)
        m = tarm[b * Tdim + t] * srcm[bn * Tdim + i_t2s];

    g_mask_all[bn * Tdim + t] = m;

    __shared__ float s1[Tdim], s2[Tdim];
    s1[t] = m;
    s2[t] = sc_t2s * m;
    __syncthreads();
    for (int off = Tdim / 2; off > 0; off >>= 1) {
        if (t < off) { s1[t] += s1[t + off]; s2[t] += s2[t + off]; }
        __syncthreads();
    }
    if (t == 0) {
        float cnt = s1[0];
        out[OFF_CNT + bn] = cnt;
        g_simavg[bn] = (cnt > 0.f) ? (s2[0] * (1.0f / 256.0f)) : 0.f;
    }
}

// ---------------------------------------------------------------------------
// Kernel D: top-K selection (stable ties) + output formatting
// ---------------------------------------------------------------------------
__global__ void topk_format(float* __restrict__ out)
{
    __shared__ int sel[KTOP];
    const int b = blockIdx.x;
    if (threadIdx.x == 0) {
        float sa[Ndim]; bool used[Ndim];
#pragma unroll
        for (int n = 0; n < Ndim; n++) { sa[n] = g_simavg[b * Ndim + n]; used[n] = false; }
        for (int k = 0; k < KTOP; k++) {
            float best = -1.f; int bi = 0;
            for (int n = 0; n < Ndim; n++)
                if (!used[n] && sa[n] > best) { best = sa[n]; bi = n; }
            used[bi] = true;
            sel[k] = bi;
            out[OFF_ID    + b * KTOP + k] = (float)bi;
            out[OFF_SCORE + b * KTOP + k] = best;
        }
    }
    __syncthreads();
    const int t = threadIdx.x;
#pragma unroll
    for (int k = 0; k < KTOP; k++) {
        const int n   = sel[k];
        const int bk  = b * KTOP + k;
        const int bnT = (b * Ndim + n) * Tdim + t;

        unsigned long long pt = g_t2sA[bnT];
        float sc = __uint_as_float((unsigned)(pt >> 32));
        int  idx = (int)(~(unsigned)pt);
        float m  = g_mask_all[bnT];

        out[OFF_SPTS + bk * Tdim + t] = sc;
        const int o = (bk * Tdim + t) * 2;
        if (m != 0.f) {
            out[OFF_TAR + o]     = (float)(t & 15);
            out[OFF_TAR + o + 1] = (float)(t >> 4);
            out[OFF_SRC + o]     = (float)(idx & 15);
            out[OFF_SRC + o + 1] = (float)(idx >> 4);
        } else {
            out[OFF_TAR + o]     = -1.f;
            out[OFF_TAR + o + 1] = -1.f;
            out[OFF_SRC + o]     = -1.f;
            out[OFF_SRC + o + 1] = -1.f;
        }
    }
}

// ---------------------------------------------------------------------------
extern "C" void kernel_launch(void* const* d_in, const int* in_sizes, int n_in,
                              void* d_out, int out_size)
{
    const float* src  = (const float*)d_in[0];
    const float* tar  = (const float*)d_in[1];
    const float* srcm = (const float*)d_in[2];
    const float* tarm = (const float*)d_in[3];
    float* out = (float*)d_out;

    static int cfg_done = 0;
    if (!cfg_done) {
        cudaFuncSetAttribute(sim_gemm, cudaFuncAttributeMaxDynamicSharedMemorySize,
                             DYN_SMEM);
        cfg_done = 1;
    }

    conv_tar<<<Bdim, 256>>>(tar, tarm);
    sim_gemm<<<BNprod * 2, 512, DYN_SMEM>>>(src, srcm);
    stage2<<<BNprod, Tdim>>>(srcm, tarm, out);
    topk_format<<<Bdim, 256>>>(out);
}

// round 9
// speedup vs baseline: 2.4521x; 1.1924x over previous
#include <cuda_runtime.h>
#include <cuda_fp16.h>
#include <cstdint>

#define Bdim   8
#define Ndim   32
#define Cdim   768
#define Tdim   256
#define KTOP   5
#define BNprod (Bdim * Ndim)

// Output layout (float32, concatenated in return-tuple order)
#define OFF_ID      0
#define OFF_SCORE   40
#define OFF_SPTS    80
#define OFF_TAR     10320
#define OFF_SRC     30800
#define OFF_CNT     51280

// ---------------- global scratch ----------------
__device__ unsigned long long g_t2sP[4][BNprod * Tdim];  // row max parts (s-quarters)
__device__ unsigned long long g_s2t[BNprod * Tdim];      // col max (complete per CTA)
__device__ float              g_mask_all[BNprod * Tdim];
__device__ float              g_simavg[BNprod];

__device__ __half g_AH[(size_t)Bdim * Cdim * Tdim];      // tar hi (3.1MB)
__device__ __half g_AL[(size_t)Bdim * Cdim * Tdim];      // tar lo
__device__ float  g_fT[Bdim * Tdim];                     // inv_norm * tar_mask

static __device__ __forceinline__ unsigned long long packsi(float score, int idx) {
    return ((unsigned long long)__float_as_uint(score) << 32) |
           (unsigned long long)(unsigned)(~idx);
}
static __device__ __forceinline__ unsigned long long umaxll(unsigned long long a,
                                                            unsigned long long b) {
    return a > b ? a : b;
}
static __device__ __forceinline__ uint32_t smem_u32(const void* p) {
    uint32_t a;
    asm("{ .reg .u64 t; cvta.to.shared.u64 t, %1; cvt.u32.u64 %0, t; }" : "=r"(a) : "l"(p));
    return a;
}
static __device__ __forceinline__ void ldm4t(uint32_t* r, uint32_t addr) {
    asm volatile("ldmatrix.sync.aligned.m8n8.x4.trans.shared.b16 {%0,%1,%2,%3}, [%4];"
                 : "=r"(r[0]), "=r"(r[1]), "=r"(r[2]), "=r"(r[3]) : "r"(addr));
}
static __device__ __forceinline__ void mma16816(float* d, const uint32_t* a,
                                                const uint32_t* b) {
    asm volatile(
        "mma.sync.aligned.m16n8k16.row.col.f32.f16.f16.f32 "
        "{%0,%1,%2,%3}, {%4,%5,%6,%7}, {%8,%9}, {%0,%1,%2,%3};"
        : "+f"(d[0]), "+f"(d[1]), "+f"(d[2]), "+f"(d[3])
        : "r"(a[0]), "r"(a[1]), "r"(a[2]), "r"(a[3]), "r"(b[0]), "r"(b[1]));
}
static __device__ __forceinline__ void cpasync16(uint32_t dst, const void* src) {
    asm volatile("cp.async.cg.shared.global [%0], [%1], 16;" :: "r"(dst), "l"(src)
                 : "memory");
}
#define CP_COMMIT()  asm volatile("cp.async.commit_group;" ::: "memory")
#define CP_WAIT(n)   asm volatile("cp.async.wait_group %0;" :: "n"(n) : "memory")

static __device__ __forceinline__ void sts64(uint32_t addr, uint32_t r0, uint32_t r1) {
    asm volatile("st.shared.v2.b32 [%0], {%1, %2};" :: "r"(addr), "r"(r0), "r"(r1)
                 : "memory");
}
static __device__ __forceinline__ void cvt4(float4 v, float* sq,
                                            uint32_t& hi0, uint32_t& hi1,
                                            uint32_t& lo0, uint32_t& lo1) {
    sq[0] = fmaf(v.x, v.x, sq[0]);
    sq[1] = fmaf(v.y, v.y, sq[1]);
    sq[2] = fmaf(v.z, v.z, sq[2]);
    sq[3] = fmaf(v.w, v.w, sq[3]);
    __half hx = __float2half_rn(v.x), hy = __float2half_rn(v.y);
    __half hz = __float2half_rn(v.z), hw = __float2half_rn(v.w);
    __half lx = __float2half_rn(v.x - __half2float(hx));
    __half ly = __float2half_rn(v.y - __half2float(hy));
    __half lz = __float2half_rn(v.z - __half2float(hz));
    __half lw = __float2half_rn(v.w - __half2float(hw));
    hi0 = __half_as_ushort(hx) | ((uint32_t)__half_as_ushort(hy) << 16);
    hi1 = __half_as_ushort(hz) | ((uint32_t)__half_as_ushort(hw) << 16);
    lo0 = __half_as_ushort(lx) | ((uint32_t)__half_as_ushort(ly) << 16);
    lo1 = __half_as_ushort(lz) | ((uint32_t)__half_as_ushort(lw) << 16);
}

// ---------------------------------------------------------------------------
// Kernel A: tar fp32 -> fp16 hi/lo planes + exact tar norms (8 blocks)
// ---------------------------------------------------------------------------
__global__ __launch_bounds__(256)
void conv_tar(const float* __restrict__ tar, const float* __restrict__ tarm)
{
    const int b = blockIdx.x;
    const int t = threadIdx.x;
    const float* p  = tar  + (size_t)b * Cdim * Tdim + t;
    __half* ph = g_AH + (size_t)b * Cdim * Tdim + t;
    __half* pl = g_AL + (size_t)b * Cdim * Tdim + t;

    float sq = 0.f;
#pragma unroll 8
    for (int c = 0; c < Cdim; c++) {
        float x = __ldg(p + (size_t)c * Tdim);
        sq = fmaf(x, x, sq);
        __half h = __float2half_rn(x);
        __half l = __float2half_rn(x - __half2float(h));
        ph[(size_t)c * Tdim] = h;
        pl[(size_t)c * Tdim] = l;
    }
    float inv = 1.0f / fmaxf(sqrtf(sq), 1e-12f);
    g_fT[b * Tdim + t] = inv * tarm[b * Tdim + t];
}

// ---------------------------------------------------------------------------
// Kernel B: M=256 x N=64 GEMM, 1024 CTAs, 256 threads, 2 CTAs/SM.
// A: 3-stage cp.async of fp16 planes (16KB/stage). B: fp32 LDG->cvt->STS,
// 2-buffer (4KB/buf), each src element touched exactly once.
// ---------------------------------------------------------------------------
#define ASTG      16384     // A stage: hi 8KB + lo 8KB
#define BBASE     49152
#define BBUF      4096      // B buf: hi 2KB + lo 2KB
#define DYN_SMEM  (BBASE + 2 * BBUF)   // 57344

__global__ __launch_bounds__(256, 2)
void sim_gemm(const float* __restrict__ src, const float* __restrict__ srcm)
{
    extern __shared__ char dsm[];
    __shared__ float fA[256], fB[64], fBsq[64];
    __shared__ unsigned long long rowp[256], colp[64];

    const uint32_t sb = smem_u32(dsm);
    const int tid  = threadIdx.x;
    const int w    = tid >> 5;
    const int lane = tid & 31;
    const int blk  = blockIdx.x;
    const int bn   = blk >> 2;
    const int sq4  = blk & 3;          // s-quarter
    const int s0   = sq4 << 6;
    const int b    = bn >> 5;

    fA[tid] = g_fT[b * Tdim + tid];
    rowp[tid] = 0ULL;
    if (tid < 64) { fBsq[tid] = 0.f; colp[tid] = 0ULL; }

    // A cp.async mapping: k = tid>>4, two 16B units u0, u0+1 per plane
    const int ka = tid >> 4;
    const int u0 = (tid & 15) * 2;
    const __half* gAbase = g_AH + (size_t)b * Cdim * Tdim + (size_t)ka * Tdim;
    const __half* gAbaseL = g_AL + (size_t)b * Cdim * Tdim + (size_t)ka * Tdim;
    const size_t gstep_h = (size_t)16 * Tdim;
    uint32_t adst0 = (uint32_t)ka * 512 +
                     (uint32_t)(((u0 & 24) | ((u0 ^ ka) & 7)) << 4);
    uint32_t adst1 = (uint32_t)ka * 512 +
                     (uint32_t)((((u0 + 1) & 24) | (((u0 + 1) ^ ka) & 7)) << 4);

    // B mapping: k = tid>>4, q = tid&15, 4 floats at s = q*4
    const int q = tid & 15;
    const float* gB = src + (size_t)bn * Cdim * Tdim + (size_t)ka * Tdim + s0 + q * 4;
    const uint32_t bsts = (uint32_t)ka * 128 +
                          (uint32_t)(((q >> 1) ^ (ka & 7)) << 4) + (q & 1) * 8;

    // warp tile 64x32: wm in [0,4) m-groups, wn in [0,2) n-groups
    const int wm = w & 3;
    const int wn = w >> 2;
    const int warp_m0 = wm * 64;
    const int warp_n0 = wn * 32;

    // ldmatrix offsets (A plane row = 512B, B plane row = 128B)
    const int krA = (lane & 7) + ((lane >> 4) << 3);
    const int mA8 = ((lane >> 3) & 1) << 3;
    uint32_t aoff[4];
#pragma unroll
    for (int mi = 0; mi < 4; mi++) {
        int mcol = warp_m0 + mi * 16 + mA8;
        aoff[mi] = (uint32_t)krA * 512 + (uint32_t)(((mcol >> 3) ^ (krA & 7)) << 4);
    }
    const int krB = (lane & 7) + (((lane >> 3) & 1) << 3);
    const int nB8 = ((lane >> 4) & 1) << 3;
    uint32_t boff[2];
#pragma unroll
    for (int t2 = 0; t2 < 2; t2++) {
        int ncol = warp_n0 + t2 * 16 + nB8;
        boff[t2] = (uint32_t)krB * 128 + (uint32_t)(((ncol >> 3) ^ (krB & 7)) << 4);
    }

    float acc[4][4][4];
#pragma unroll
    for (int i = 0; i < 4; i++)
#pragma unroll
        for (int j = 0; j < 4; j++)
#pragma unroll
            for (int e = 0; e < 4; e++) acc[i][j][e] = 0.f;

    float sqr[4] = {0.f, 0.f, 0.f, 0.f};

    // prologue: A stages 0,1; B chunk 0
#pragma unroll
    for (int pc = 0; pc < 2; pc++) {
        const uint32_t ab = sb + pc * ASTG;
        cpasync16(ab + adst0,        gAbase  + pc * gstep_h + u0 * 8);
        cpasync16(ab + adst1,        gAbase  + pc * gstep_h + (u0 + 1) * 8);
        cpasync16(ab + 8192 + adst0, gAbaseL + pc * gstep_h + u0 * 8);
        cpasync16(ab + 8192 + adst1, gAbaseL + pc * gstep_h + (u0 + 1) * 8);
        CP_COMMIT();
    }
    float4 rb = *(const float4*)gB;

    int stage = 0;
    for (int c = 0; c < 48; c++) {
        uint32_t h0, h1, l0, l1;
        cvt4(rb, sqr, h0, h1, l0, l1);
        const uint32_t bb = sb + BBASE + (uint32_t)(c & 1) * BBUF;
        sts64(bb + bsts,        h0, h1);
        sts64(bb + 2048 + bsts, l0, l1);
        if (c < 47) rb = *(const float4*)(gB + (size_t)(c + 1) * gstep_h);

        if (c < 47) { CP_WAIT(1); } else { CP_WAIT(0); }
        __syncthreads();

        const uint32_t abase = sb + (uint32_t)stage * ASTG;
        uint32_t Bh[2][4], Bl[2][4];
#pragma unroll
        for (int t2 = 0; t2 < 2; t2++) {
            ldm4t(Bh[t2], bb + boff[t2]);
            ldm4t(Bl[t2], bb + 2048 + boff[t2]);
        }
#pragma unroll
        for (int mi = 0; mi < 4; mi++) {
            uint32_t Ah[4], Al[4];
            ldm4t(Ah, abase + aoff[mi]);
            ldm4t(Al, abase + 8192 + aoff[mi]);
#pragma unroll
            for (int ni = 0; ni < 4; ni++) {
                const uint32_t* bh = &Bh[ni >> 1][(ni & 1) * 2];
                const uint32_t* bl = &Bl[ni >> 1][(ni & 1) * 2];
                mma16816(acc[mi][ni], Ah, bh);
                mma16816(acc[mi][ni], Ah, bl);
                mma16816(acc[mi][ni], Al, bh);
            }
        }

        if (c + 2 < 48) {
            int ps = stage + 2;
            if (ps >= 3) ps -= 3;
            const uint32_t nb = sb + (uint32_t)ps * ASTG;
            const size_t go = (size_t)(c + 2) * gstep_h;
            cpasync16(nb + adst0,        gAbase  + go + u0 * 8);
            cpasync16(nb + adst1,        gAbase  + go + (u0 + 1) * 8);
            cpasync16(nb + 8192 + adst0, gAbaseL + go + u0 * 8);
            cpasync16(nb + 8192 + adst1, gAbaseL + go + (u0 + 1) * 8);
            CP_COMMIT();
        }
        stage = (stage + 1 == 3) ? 0 : stage + 1;
    }

    // src norms (s-quarter complete in this CTA)
#pragma unroll
    for (int j = 0; j < 4; j++) atomicAdd(&fBsq[q * 4 + j], sqr[j]);
    __syncthreads();
    if (tid < 64) {
        float inv = 1.0f / fmaxf(sqrtf(fBsq[tid]), 1e-12f);
        fB[tid] = inv * srcm[bn * Tdim + s0 + tid];
    }
    __syncthreads();

    // epilogue: scale + threshold + packed dual max/argmax
    const int qrow = lane >> 2;
    const int qcol = (lane & 3) * 2;
    unsigned long long rmax[8], cmax[8];
#pragma unroll
    for (int i = 0; i < 8; i++) { rmax[i] = 0ULL; cmax[i] = 0ULL; }

#pragma unroll
    for (int mi = 0; mi < 4; mi++) {
        const int m0l = warp_m0 + mi * 16 + qrow;       // global t
        const float fa0 = fA[m0l], fa1 = fA[m0l + 8];
        const int tg0 = m0l, tg1 = m0l + 8;
#pragma unroll
        for (int ni = 0; ni < 4; ni++) {
            const int n0l = warp_n0 + ni * 8 + qcol;    // local s in [0,64)
            const float fb0 = fB[n0l], fb1 = fB[n0l + 1];
            const int sg0 = s0 + n0l, sg1 = sg0 + 1;    // global s
            const float* a = acc[mi][ni];
            float v00 = a[0] * fa0 * fb0; if (v00 < 0.05f) v00 = 0.f;
            float v01 = a[1] * fa0 * fb1; if (v01 < 0.05f) v01 = 0.f;
            float v10 = a[2] * fa1 * fb0; if (v10 < 0.05f) v10 = 0.f;
            float v11 = a[3] * fa1 * fb1; if (v11 < 0.05f) v11 = 0.f;
            rmax[mi * 2 + 0] = umaxll(rmax[mi * 2 + 0],
                                      umaxll(packsi(v00, sg0), packsi(v01, sg1)));
            rmax[mi * 2 + 1] = umaxll(rmax[mi * 2 + 1],
                                      umaxll(packsi(v10, sg0), packsi(v11, sg1)));
            cmax[ni * 2 + 0] = umaxll(cmax[ni * 2 + 0],
                                      umaxll(packsi(v00, tg0), packsi(v10, tg1)));
            cmax[ni * 2 + 1] = umaxll(cmax[ni * 2 + 1],
                                      umaxll(packsi(v01, tg0), packsi(v11, tg1)));
        }
    }
#pragma unroll
    for (int mi = 0; mi < 4; mi++) {
        atomicMax(&rowp[warp_m0 + mi * 16 + qrow],     rmax[mi * 2 + 0]);
        atomicMax(&rowp[warp_m0 + mi * 16 + qrow + 8], rmax[mi * 2 + 1]);
    }
#pragma unroll
    for (int ni = 0; ni < 4; ni++) {
        atomicMax(&colp[warp_n0 + ni * 8 + qcol],     cmax[ni * 2 + 0]);
        atomicMax(&colp[warp_n0 + ni * 8 + qcol + 1], cmax[ni * 2 + 1]);
    }
    __syncthreads();

    g_t2sP[sq4][bn * Tdim + tid] = rowp[tid];
    if (tid < 64) g_s2t[bn * Tdim + s0 + tid] = colp[tid];
}

// ---------------------------------------------------------------------------
// Kernel C: merge row quarters + cycle consistency + counts + sim_avg
// ---------------------------------------------------------------------------
__global__ void stage2(const float* __restrict__ srcm,
                       const float* __restrict__ tarm,
                       float* __restrict__ out)
{
    const int bn = blockIdx.x;
    const int b  = bn >> 5;
    const int t  = threadIdx.x;

    unsigned long long pt = umaxll(
        umaxll(g_t2sP[0][bn * Tdim + t], g_t2sP[1][bn * Tdim + t]),
        umaxll(g_t2sP[2][bn * Tdim + t], g_t2sP[3][bn * Tdim + t]));
    g_t2sP[0][bn * Tdim + t] = pt;                    // combined, for topk
    float sc_t2s = __uint_as_float((unsigned)(pt >> 32));
    int   i_t2s  = (int)(~(unsigned)pt);

    int i_s2t_here = (int)(~(unsigned)g_s2t[bn * Tdim + t]);

    unsigned long long psi = g_s2t[bn * Tdim + i_t2s];
    float sc_s2t_i = __uint_as_float((unsigned)(psi >> 32));
    int   i_s2s    = (int)(~(unsigned)psi);

    int dx = (i_s2s & 15) - (t & 15);
    int dy = (i_s2s >> 4) - (t >> 4);
    bool cyc  = (dx * dx + dy * dy <= 4) && (sc_s2t_i >= 0.05f);
    bool msim = (sc_t2s >= 0.05f);

    float m = 0.f;
    if (msim && cyc && i_s2t_here != 0 && i_t2s != 0)
        m = tarm[b * Tdim + t] * srcm[bn * Tdim + i_t2s];

    g_mask_all[bn * Tdim + t] = m;

    __shared__ float s1[Tdim], s2[Tdim];
    s1[t] = m;
    s2[t] = sc_t2s * m;
    __syncthreads();
    for (int off = Tdim / 2; off > 0; off >>= 1) {
        if (t < off) { s1[t] += s1[t + off]; s2[t] += s2[t + off]; }
        __syncthreads();
    }
    if (t == 0) {
        float cnt = s1[0];
        out[OFF_CNT + bn] = cnt;
        g_simavg[bn] = (cnt > 0.f) ? (s2[0] * (1.0f / 256.0f)) : 0.f;
    }
}

// ---------------------------------------------------------------------------
// Kernel D: top-K selection (stable ties) + output formatting
// ---------------------------------------------------------------------------
__global__ void topk_format(float* __restrict__ out)
{
    __shared__ int sel[KTOP];
    const int b = blockIdx.x;
    if (threadIdx.x == 0) {
        float sa[Ndim]; bool used[Ndim];
#pragma unroll
        for (int n = 0; n < Ndim; n++) { sa[n] = g_simavg[b * Ndim + n]; used[n] = false; }
        for (int k = 0; k < KTOP; k++) {
            float best = -1.f; int bi = 0;
            for (int n = 0; n < Ndim; n++)
                if (!used[n] && sa[n] > best) { best = sa[n]; bi = n; }
            used[bi] = true;
            sel[k] = bi;
            out[OFF_ID    + b * KTOP + k] = (float)bi;
            out[OFF_SCORE + b * KTOP + k] = best;
        }
    }
    __syncthreads();
    const int t = threadIdx.x;
#pragma unroll
    for (int k = 0; k < KTOP; k++) {
        const int n   = sel[k];
        const int bk  = b * KTOP + k;
        const int bnT = (b * Ndim + n) * Tdim + t;

        unsigned long long pt = g_t2sP[0][bnT];
        float sc = __uint_as_float((unsigned)(pt >> 32));
        int  idx = (int)(~(unsigned)pt);
        float m  = g_mask_all[bnT];

        out[OFF_SPTS + bk * Tdim + t] = sc;
        const int o = (bk * Tdim + t) * 2;
        if (m != 0.f) {
            out[OFF_TAR + o]     = (float)(t & 15);
            out[OFF_TAR + o + 1] = (float)(t >> 4);
            out[OFF_SRC + o]     = (float)(idx & 15);
            out[OFF_SRC + o + 1] = (float)(idx >> 4);
        } else {
            out[OFF_TAR + o]     = -1.f;
            out[OFF_TAR + o + 1] = -1.f;
            out[OFF_SRC + o]     = -1.f;
            out[OFF_SRC + o + 1] = -1.f;
        }
    }
}

// ---------------------------------------------------------------------------
extern "C" void kernel_launch(void* const* d_in, const int* in_sizes, int n_in,
                              void* d_out, int out_size)
{
    const float* src  = (const float*)d_in[0];
    const float* tar  = (const float*)d_in[1];
    const float* srcm = (const float*)d_in[2];
    const float* tarm = (const float*)d_in[3];
    float* out = (float*)d_out;

    static int cfg_done = 0;
    if (!cfg_done) {
        cudaFuncSetAttribute(sim_gemm, cudaFuncAttributeMaxDynamicSharedMemorySize,
                             DYN_SMEM);
        cfg_done = 1;
    }

    conv_tar<<<Bdim, 256>>>(tar, tarm);
    sim_gemm<<<BNprod * 4, 256, DYN_SMEM>>>(src, srcm);
    stage2<<<BNprod, Tdim>>>(srcm, tarm, out);
    topk_format<<<Bdim, 256>>>(out);
}